// round 15
// baseline (speedup 1.0000x reference)
#include <cuda_runtime.h>
#include <math_constants.h>

#define NEMB  8192
#define NTOK  32768             // 8 * 4096
#define NBLK  148
#define NTHR  896               // 28 warps
#define CAP   1024              // staged capacity (mean ~750)
#define THETA 8.0f              // ||e||^2 cutoff
#define NB2   64
#define WID2  0.5625f           // bin width over n2 in [8, 44)
#define IW2   (1.0f / 0.5625f)
#define SQ8G  (2.82842712f * 1.000002f)   // guarded sqrt(THETA)
#define NUBS  (CAP / 32 + 1)

__device__ float4 d_tbl[CAP];   // globally bin-sorted candidates (desc norm)
__device__ int    d_sidx[CAP];
__device__ float  d_ub[NUBS];   // superstep-boundary upper bounds
__device__ int    d_cnt;        // written fresh by kernel A every call
__device__ float  d_part[NBLK];
__device__ int    d_done;       // zero-init; reset by finalizer each call

// ---- Kernel A: single block stages AND sorts the candidate list ----
__global__ __launch_bounds__(1024, 1)
void vq_stage_sort(const float4* __restrict__ e4) {
    __shared__ float4 s_stage[CAP];
    __shared__ int    s_sid[CAP];
    __shared__ int    s_hist[NB2], s_soff[NB2], s_scur[NB2];
    __shared__ int    s_cnt;
    const int t = threadIdx.x, lane = t & 31, wid = t >> 5;

    if (t < NB2) { s_hist[t] = 0; s_scur[t] = 0; }
    if (t == 0) s_cnt = 0;
    __syncthreads();

    #pragma unroll
    for (int r = 0; r < 8; r++) {                     // 8 loads deep (MLP)
        int i = t + r * 1024;
        float4 e = e4[i];
        float n2 = e.x*e.x + e.y*e.y + e.z*e.z + e.w*e.w;
        bool c = (n2 >= THETA);
        unsigned m = __ballot_sync(0xFFFFFFFFu, c);
        int base = 0;
        if (lane == 0 && m) base = atomicAdd(&s_cnt, __popc(m));
        base = __shfl_sync(0xFFFFFFFFu, base, 0);
        if (c) {
            int pos = base + __popc(m & ((1u << lane) - 1u));
            if (pos < CAP) {
                s_stage[pos] = e; s_sid[pos] = i;
                int raw = (int)((n2 - THETA) * IW2);
                raw = raw < 0 ? 0 : (raw > NB2 - 1 ? NB2 - 1 : raw);
                atomicAdd(&s_hist[(NB2 - 1) - raw], 1);
            }
        }
    }
    __syncthreads();

    // exclusive prefix over 64 bins (warp 0)
    if (wid == 0) {
        int a = s_hist[lane], b = s_hist[lane + 32];
        int va = a, vb = b;
        #pragma unroll
        for (int o = 1; o < 32; o <<= 1) {
            int u = __shfl_up_sync(0xFFFFFFFFu, va, o); if (lane >= o) va += u;
            int w = __shfl_up_sync(0xFFFFFFFFu, vb, o); if (lane >= o) vb += w;
        }
        int tot = __shfl_sync(0xFFFFFFFFu, va, 31);
        s_soff[lane]      = va - a;
        s_soff[lane + 32] = tot + vb - b;
    }
    __syncthreads();

    // scatter staged -> globally sorted table + superstep ub
    int cnt = s_cnt < CAP ? s_cnt : CAP;
    if (t < cnt) {
        float4 e = s_stage[t];
        float n2 = e.x*e.x + e.y*e.y + e.z*e.z + e.w*e.w;
        int raw = (int)((n2 - THETA) * IW2);
        raw = raw < 0 ? 0 : (raw > NB2 - 1 ? NB2 - 1 : raw);
        int b = (NB2 - 1) - raw;
        int pos = s_soff[b] + atomicAdd(&s_scur[b], 1);
        if (pos < CAP) {
            d_tbl[pos]  = e;
            d_sidx[pos] = s_sid[t];
            if ((pos & 31) == 0)        // ub for all slots >= pos
                d_ub[pos >> 5] = (b == 0) ? CUDART_INF_F
                    : sqrtf(THETA + (float)(NB2 - b) * WID2) * 1.000002f;
        }
    }
    if (t == 0) d_cnt = s_cnt;          // fresh every call: no reset needed
}

// ---- Kernel B: copy sorted table to smem, pruned scan, loss ----
__global__ __launch_bounds__(NTHR, 1)
void vq_main_kernel(const float4* __restrict__ x4,
                    const float4* __restrict__ e4,
                    float* __restrict__ out) {
    __shared__ float4 s_tbl[CAP];
    __shared__ int    s_sidx[CAP];
    __shared__ float  s_ubs[NUBS];
    __shared__ float  wred[NTHR / 32];
    __shared__ int    s_last;

    const int t    = threadIdx.x;
    const int lane = t & 31;
    const int wid  = t >> 5;
    const int sub  = lane & 3;
    const int tok  = ((int)blockIdx.x * 28 + wid) * 8 + (lane >> 2);
    const bool act = tok < NTOK;

    float4 xv = act ? x4[tok] : make_float4(0.f, 0.f, 0.f, 0.f);
    const float nx = sqrtf(xv.x*xv.x + xv.y*xv.y + xv.z*xv.z + xv.w*xv.w)
                     * 1.000002f;                     // fp-guarded |x|

    const int  cnt_all = d_cnt;
    const bool over    = cnt_all > CAP;               // ~never: exact fallback
    const int  cnt     = cnt_all < CAP ? cnt_all : CAP;

    // phase 1: straight copy of the pre-sorted table (no sort work)
    if (t == 0) s_last = 0;
    #pragma unroll
    for (int r = 0; r < 2; r++) {
        int i = t + r * NTHR;
        if (i < cnt) { s_tbl[i] = d_tbl[i]; s_sidx[i] = d_sidx[i]; }
    }
    if (t < NUBS) s_ubs[t] = d_ub[t];
    __syncthreads();

    // phase 2: pruned scan, 4 lanes/token, stop test every 64 slots
    float best = act ? -CUDART_INF_F : CUDART_INF_F;
    int bidx = NEMB;
    const int nsl = (cnt + 63) & ~63;                 // <= CAP

    for (int p = 0; p < nsl; p += 64) {
        float ubn = (p + 64 >= cnt) ? SQ8G : s_ubs[(p >> 5) + 2];
        float d[16];
        #pragma unroll
        for (int h = 0; h < 2; h++)
            #pragma unroll
            for (int i = 0; i < 8; i++) {
                int slot = p + h * 32 + sub + 4 * i;  // 4 words/warp: broadcast
                float4 e = s_tbl[slot];
                float dd = fmaf(xv.x, e.x, fmaf(xv.y, e.y, fmaf(xv.z, e.z, xv.w * e.w)));
                d[h * 8 + i] = (slot < cnt) ? dd : -CUDART_INF_F;
            }
        float om = d[0];
        #pragma unroll
        for (int i = 1; i < 16; i++) om = fmaxf(om, d[i]);
        if (om >= best) {
            // rare slow path: exact first-max update, original-id tie-break
            #pragma unroll
            for (int h = 0; h < 2; h++)
                #pragma unroll
                for (int i = 0; i < 8; i++) {
                    int slot = p + h * 32 + sub + 4 * i;
                    int id = (slot < cnt) ? s_sidx[slot] : NEMB;
                    float dv = d[h * 8 + i];
                    if (dv > best || (dv == best && id < bidx)) {
                        best = dv; bidx = id;
                    }
                }
        }
        float cb = best;                 // quad-combined best value
        cb = fmaxf(cb, __shfl_xor_sync(0xFFFFFFFFu, cb, 1));
        cb = fmaxf(cb, __shfl_xor_sync(0xFFFFFFFFu, cb, 2));
        // remaining slots <= ubn; sub-theta mass <= SQ8G <= ubn
        if (!over && __all_sync(0xFFFFFFFFu, ubn * nx < cb)) break;
    }

    // final certificate; ~never false for real data
    float cbf = best;
    cbf = fmaxf(cbf, __shfl_xor_sync(0xFFFFFFFFu, cbf, 1));
    cbf = fmaxf(cbf, __shfl_xor_sync(0xFFFFFFFFu, cbf, 2));
    bool needFB = over ? act : !(SQ8G * nx < cbf);

    // exact warp-cooperative full-table fallback (correctness backstop)
    unsigned m = __ballot_sync(0xFFFFFFFFu, needFB);
    while (m) {
        int l = __ffs(m) - 1; int q = l >> 2;
        m &= ~(0xFu << (q << 2));
        int ol = q << 2;
        float tx = __shfl_sync(0xFFFFFFFFu, xv.x, ol);
        float ty = __shfl_sync(0xFFFFFFFFu, xv.y, ol);
        float tz = __shfl_sync(0xFFFFFFFFu, xv.z, ol);
        float tw = __shfl_sync(0xFFFFFFFFu, xv.w, ol);
        float lb = -CUDART_INF_F;
        int lid = NEMB;
        for (int pp = 0; pp < NEMB; pp += 256) {
            #pragma unroll
            for (int i = 0; i < 8; i++) {
                int slot = pp + lane + (i << 5);
                float4 e = e4[slot];
                float dd = fmaf(tx, e.x, fmaf(ty, e.y, fmaf(tz, e.z, tw * e.w)));
                if (dd > lb || (dd == lb && slot < lid)) { lb = dd; lid = slot; }
            }
        }
        #pragma unroll
        for (int o = 16; o; o >>= 1) {
            float vo = __shfl_xor_sync(0xFFFFFFFFu, lb, o);
            int   io = __shfl_xor_sync(0xFFFFFFFFu, lid, o);
            if (vo > lb || (vo == lb && io < lid)) { lb = vo; lid = io; }
        }
        if ((lane >> 2) == q) {
            if (lb > best || (lb == best && lid < bidx)) { best = lb; bidx = lid; }
        }
    }

    // merge quad lanes: max value, ties -> lowest original index
    #pragma unroll
    for (int o = 1; o <= 2; o <<= 1) {
        float vo = __shfl_xor_sync(0xFFFFFFFFu, best, o);
        int   io = __shfl_xor_sync(0xFFFFFFFFu, bidx, o);
        if (vo > best || (vo == best && io < bidx)) { best = vo; bidx = io; }
    }

    float lsum = 0.0f;
    if (act && sub == 0) {
        float4 e = e4[bidx];
        lsum = fabsf(xv.x - e.x) + fabsf(xv.y - e.y)
             + fabsf(xv.z - e.z) + fabsf(xv.w - e.w);
    }

    // reduce: warp -> block
    #pragma unroll
    for (int o = 16; o; o >>= 1)
        lsum += __shfl_down_sync(0xFFFFFFFFu, lsum, o);
    if (lane == 0) wred[wid] = lsum;
    __syncthreads();

    // block partial -> d_part; last-arriving block finalizes + resets
    if (t == 0) {
        float s = 0.0f;
        #pragma unroll
        for (int i = 0; i < NTHR / 32; i++) s += wred[i];
        d_part[blockIdx.x] = s;
        __threadfence();
        if (atomicAdd(&d_done, 1) == NBLK - 1) s_last = 1;
    }
    __syncthreads();
    if (s_last && wid == 0) {
        float s = 0.0f;
        for (int i = lane; i < NBLK; i += 32) s += d_part[i];
        #pragma unroll
        for (int o = 16; o; o >>= 1)
            s += __shfl_down_sync(0xFFFFFFFFu, s, o);
        if (lane == 0) {
            out[0] = s * (2.0f / (float)(NTOK * 4));  // both L1 terms equal
            d_done = 0;                               // reset for graph replay
        }
    }
}

extern "C" void kernel_launch(void* const* d_in, const int* in_sizes, int n_in,
                              void* d_out, int out_size) {
    const float4* x   = (const float4*)d_in[0];   // [8,4096,4] f32
    const float4* emb = (const float4*)d_in[1];   // [8192,4] f32
    float* out = (float*)d_out;

    vq_stage_sort<<<1, 1024>>>(emb);
    vq_main_kernel<<<NBLK, NTHR>>>(x, emb, out);
}

// round 16
// speedup vs baseline: 1.1946x; 1.1946x over previous
#include <cuda_runtime.h>
#include <math_constants.h>

#define NEMB  8192
#define NTOK  32768             // 8 * 4096
#define NBLK  148
#define NTHR  896               // 28 warps
#define NRUN  32                // staging runs (one per A block)
#define RCAP  64                // per-run capacity (mean ~23, +8.8 sigma)
#define CAP   1024              // compact capacity
#define THETA 8.0f              // ||e||^2 cutoff
#define NB2   64
#define WID2  0.5625f           // bin width over n2 in [8, 44)
#define IW2   (1.0f / 0.5625f)
#define SQ8G  (2.82842712f * 1.000002f)   // guarded sqrt(THETA)
#define NUBS  (CAP / 32 + 1)

__device__ float4 d_stage[NRUN * RCAP];   // fully rewritten by A each call
__device__ int    d_sid[NRUN * RCAP];
__device__ int    d_bcnt[NRUN];           // fully rewritten by A each call

// ---- Kernel A: atomic-free staging into per-block runs; zeroes out ----
__global__ __launch_bounds__(256, 1)
void vq_stage(const float4* __restrict__ e4, float* __restrict__ out) {
    __shared__ float4 s_st[RCAP];
    __shared__ int    s_id[RCAP];
    __shared__ int    s_n;
    const int t = threadIdx.x, lane = t & 31, b = blockIdx.x;
    if (t == 0) { s_n = 0; if (b == 0) out[0] = 0.0f; }
    __syncthreads();

    int i = b * 256 + t;
    float4 e = e4[i];
    float n2 = e.x*e.x + e.y*e.y + e.z*e.z + e.w*e.w;
    bool c = (n2 >= THETA);
    unsigned m = __ballot_sync(0xFFFFFFFFu, c);
    int base = 0;
    if (lane == 0 && m) base = atomicAdd(&s_n, __popc(m));   // 8 smem atomics
    base = __shfl_sync(0xFFFFFFFFu, base, 0);
    if (c) {
        int p = base + __popc(m & ((1u << lane) - 1u));
        if (p < RCAP) { s_st[p] = e; s_id[p] = i; }
    }
    __syncthreads();
    int n = s_n < RCAP ? s_n : RCAP;
    if (t < n) { d_stage[b * RCAP + t] = s_st[t]; d_sid[b * RCAP + t] = s_id[t]; }
    if (t == 0) d_bcnt[b] = s_n;          // may exceed RCAP -> over in B
}

// ---- Kernel B: compact+sort in smem, pruned scan, direct atomic loss ----
__global__ __launch_bounds__(NTHR, 1)
void vq_main_kernel(const float4* __restrict__ x4,
                    const float4* __restrict__ e4,
                    float* __restrict__ out) {
    __shared__ float4 s_stage[CAP];       // compacted (unsorted)
    __shared__ int    s_sid[CAP];
    __shared__ float4 s_tbl[CAP];         // bin-sorted (desc norm)
    __shared__ int    s_sidx[CAP];
    __shared__ int    s_bc[NRUN], s_bo[NRUN + 1];
    __shared__ int    s_hist[NB2], s_soff[NB2], s_scur[NB2];
    __shared__ float  s_ubs[NUBS];
    __shared__ float  wred[NTHR / 32];
    __shared__ int    s_over;

    const int t    = threadIdx.x;
    const int lane = t & 31;
    const int wid  = t >> 5;
    const int sub  = lane & 3;
    const int tok  = ((int)blockIdx.x * 28 + wid) * 8 + (lane >> 2);
    const bool act = tok < NTOK;

    float4 xv = act ? x4[tok] : make_float4(0.f, 0.f, 0.f, 0.f);
    const float nx = sqrtf(xv.x*xv.x + xv.y*xv.y + xv.z*xv.z + xv.w*xv.w)
                     * 1.000002f;                     // fp-guarded |x|

    if (t < NB2) { s_hist[t] = 0; s_scur[t] = 0; }
    if (t < NRUN) s_bc[t] = d_bcnt[t];
    __syncthreads();

    // prefix over 32 run-counts (warp 0) + over flag
    if (wid == 0) {
        int c = s_bc[lane];
        bool ov = __any_sync(0xFFFFFFFFu, c > RCAP);
        int cc = c > RCAP ? RCAP : c;
        int v = cc;
        #pragma unroll
        for (int o = 1; o < 32; o <<= 1) {
            int u = __shfl_up_sync(0xFFFFFFFFu, v, o);
            if (lane >= o) v += u;
        }
        s_bo[lane] = v - cc;
        if (lane == 31) { s_bo[NRUN] = v; s_over = ov ? 1 : 0; }
    }
    __syncthreads();

    const int  cnt_all = s_bo[NRUN];
    const bool over    = s_over || (cnt_all > CAP);   // ~never
    const int  cnt     = cnt_all < CAP ? cnt_all : CAP;

    // copy ragged runs -> compact smem staging (warp w handles runs w, w+28)
    for (int b = wid; b < NRUN; b += 28) {
        int n = s_bc[b] < RCAP ? s_bc[b] : RCAP;
        int off = s_bo[b];
        for (int j = lane; j < n; j += 32) {
            int dst = off + j;
            if (dst < CAP) {
                s_stage[dst] = d_stage[b * RCAP + j];
                s_sid[dst]   = d_sid[b * RCAP + j];
            }
        }
    }
    __syncthreads();

    // histogram (validated R12/R14 path)
    #pragma unroll
    for (int r = 0; r < 2; r++) {
        int i = t + r * NTHR;
        if (i < cnt) {
            float4 e = s_stage[i];
            float n2 = e.x*e.x + e.y*e.y + e.z*e.z + e.w*e.w;
            int raw = (int)((n2 - THETA) * IW2);
            raw = raw < 0 ? 0 : (raw > NB2 - 1 ? NB2 - 1 : raw);
            atomicAdd(&s_hist[(NB2 - 1) - raw], 1);
        }
    }
    __syncthreads();

    // exclusive prefix over 64 bins (warp 0)
    if (wid == 0) {
        int a = s_hist[lane], b = s_hist[lane + 32];
        int va = a, vb = b;
        #pragma unroll
        for (int o = 1; o < 32; o <<= 1) {
            int u = __shfl_up_sync(0xFFFFFFFFu, va, o); if (lane >= o) va += u;
            int w = __shfl_up_sync(0xFFFFFFFFu, vb, o); if (lane >= o) vb += w;
        }
        int tot = __shfl_sync(0xFFFFFFFFu, va, 31);
        s_soff[lane]      = va - a;
        s_soff[lane + 32] = tot + vb - b;
    }
    __syncthreads();

    // scatter into bin-sorted order + superstep ub
    #pragma unroll
    for (int r = 0; r < 2; r++) {
        int i = t + r * NTHR;
        if (i < cnt) {
            float4 e = s_stage[i];
            float n2 = e.x*e.x + e.y*e.y + e.z*e.z + e.w*e.w;
            int raw = (int)((n2 - THETA) * IW2);
            raw = raw < 0 ? 0 : (raw > NB2 - 1 ? NB2 - 1 : raw);
            int b = (NB2 - 1) - raw;
            int pos = s_soff[b] + atomicAdd(&s_scur[b], 1);
            if (pos < CAP) {
                s_tbl[pos]  = e;
                s_sidx[pos] = s_sid[i];
                if ((pos & 31) == 0)    // ub for all slots >= pos
                    s_ubs[pos >> 5] = (b == 0) ? CUDART_INF_F
                        : sqrtf(THETA + (float)(NB2 - b) * WID2) * 1.000002f;
            }
        }
    }
    __syncthreads();

    // ---- pruned scan: 4 lanes/token; tests hoisted past first 128 slots ----
    float best = act ? -CUDART_INF_F : CUDART_INF_F;
    int bidx = NEMB;
    const int nsl = (cnt + 31) & ~31;

    for (int p = 0; p < nsl; p += 32) {
        float d[8];
        #pragma unroll
        for (int i = 0; i < 8; i++) {
            int slot = p + sub + 4 * i;               // 4 words/warp: broadcast
            float4 e = s_tbl[slot];
            float dd = fmaf(xv.x, e.x, fmaf(xv.y, e.y, fmaf(xv.z, e.z, xv.w * e.w)));
            d[i] = (slot < cnt) ? dd : -CUDART_INF_F;
        }
        float om = fmaxf(fmaxf(fmaxf(d[0], d[1]), fmaxf(d[2], d[3])),
                         fmaxf(fmaxf(d[4], d[5]), fmaxf(d[6], d[7])));
        if (om >= best) {
            // rare slow path: exact first-max update, original-id tie-break
            #pragma unroll
            for (int i = 0; i < 8; i++) {
                int slot = p + sub + 4 * i;
                int id = (slot < cnt) ? s_sidx[slot] : NEMB;
                if (d[i] > best || (d[i] == best && id < bidx)) {
                    best = d[i]; bidx = id;
                }
            }
        }
        if (p >= 96) {                    // certificate ~never passes earlier
            float ubn = (p + 32 >= cnt) ? SQ8G : s_ubs[(p >> 5) + 1];
            float cb = best;              // quad-combined best value
            cb = fmaxf(cb, __shfl_xor_sync(0xFFFFFFFFu, cb, 1));
            cb = fmaxf(cb, __shfl_xor_sync(0xFFFFFFFFu, cb, 2));
            // remaining slots <= ubn; sub-theta mass <= SQ8G <= ubn
            if (!over && __all_sync(0xFFFFFFFFu, ubn * nx < cb)) break;
        }
    }

    // final certificate; ~never false for real data
    float cbf = best;
    cbf = fmaxf(cbf, __shfl_xor_sync(0xFFFFFFFFu, cbf, 1));
    cbf = fmaxf(cbf, __shfl_xor_sync(0xFFFFFFFFu, cbf, 2));
    bool needFB = over ? act : !(SQ8G * nx < cbf);

    // exact warp-cooperative full-table fallback (correctness backstop)
    unsigned m = __ballot_sync(0xFFFFFFFFu, needFB);
    while (m) {
        int l = __ffs(m) - 1; int q = l >> 2;
        m &= ~(0xFu << (q << 2));
        int ol = q << 2;
        float tx = __shfl_sync(0xFFFFFFFFu, xv.x, ol);
        float ty = __shfl_sync(0xFFFFFFFFu, xv.y, ol);
        float tz = __shfl_sync(0xFFFFFFFFu, xv.z, ol);
        float tw = __shfl_sync(0xFFFFFFFFu, xv.w, ol);
        float lb = -CUDART_INF_F;
        int lid = NEMB;
        for (int pp = 0; pp < NEMB; pp += 256) {
            #pragma unroll
            for (int i = 0; i < 8; i++) {
                int slot = pp + lane + (i << 5);
                float4 e = e4[slot];
                float dd = fmaf(tx, e.x, fmaf(ty, e.y, fmaf(tz, e.z, tw * e.w)));
                if (dd > lb || (dd == lb && slot < lid)) { lb = dd; lid = slot; }
            }
        }
        #pragma unroll
        for (int o = 16; o; o >>= 1) {
            float vo = __shfl_xor_sync(0xFFFFFFFFu, lb, o);
            int   io = __shfl_xor_sync(0xFFFFFFFFu, lid, o);
            if (vo > lb || (vo == lb && io < lid)) { lb = vo; lid = io; }
        }
        if ((lane >> 2) == q) {
            if (lb > best || (lb == best && lid < bidx)) { best = lb; bidx = lid; }
        }
    }

    // merge quad lanes: max value, ties -> lowest original index
    #pragma unroll
    for (int o = 1; o <= 2; o <<= 1) {
        float vo = __shfl_xor_sync(0xFFFFFFFFu, best, o);
        int   io = __shfl_xor_sync(0xFFFFFFFFu, bidx, o);
        if (vo > best || (vo == best && io < bidx)) { best = vo; bidx = io; }
    }

    float lsum = 0.0f;
    if (act && sub == 0) {
        float4 e = e4[bidx];
        lsum = fabsf(xv.x - e.x) + fabsf(xv.y - e.y)
             + fabsf(xv.z - e.z) + fabsf(xv.w - e.w);
    }

    // reduce: warp -> block -> ONE direct global atomic (out zeroed by A)
    #pragma unroll
    for (int o = 16; o; o >>= 1)
        lsum += __shfl_down_sync(0xFFFFFFFFu, lsum, o);
    if (lane == 0) wred[wid] = lsum;
    __syncthreads();
    if (t == 0) {
        float s = 0.0f;
        #pragma unroll
        for (int i = 0; i < NTHR / 32; i++) s += wred[i];
        atomicAdd(out, s * (2.0f / (float)(NTOK * 4)));  // both L1 terms equal
    }
}

extern "C" void kernel_launch(void* const* d_in, const int* in_sizes, int n_in,
                              void* d_out, int out_size) {
    const float4* x   = (const float4*)d_in[0];   // [8,4096,4] f32
    const float4* emb = (const float4*)d_in[1];   // [8192,4] f32
    float* out = (float*)d_out;

    vq_stage<<<NRUN, 256>>>(emb, out);
    vq_main_kernel<<<NBLK, NTHR>>>(x, emb, out);
}

// round 17
// speedup vs baseline: 1.2552x; 1.0507x over previous
#include <cuda_runtime.h>
#include <math_constants.h>

#define NEMB  8192
#define NTOK  32768             // 8 * 4096
#define NBLK  148
#define NTHR  896               // 28 warps
#define NRUN  256               // one run per A-warp
#define RCAP  16                // per-warp capacity (mean ~2.9, +7.9 sigma)
#define CAP   1024              // compact capacity
#define THETA 8.0f              // ||e||^2 cutoff
#define NB2   64
#define WID2  0.5625f           // bin width over n2 in [8, 44)
#define IW2   (1.0f / 0.5625f)
#define SQ8G  (2.82842712f * 1.000002f)   // guarded sqrt(THETA)
#define NUBS  (CAP / 32 + 1)

__device__ float4 d_stage[NRUN * RCAP];   // rewritten by A each call
__device__ int    d_sid[NRUN * RCAP];
__device__ int    d_bcnt[NRUN];           // rewritten by A each call

// ---- Kernel A: atomic-free, smem-free, sync-free staging ----
__global__ __launch_bounds__(256, 1)
void vq_stage(const float4* __restrict__ e4, float* __restrict__ out) {
    const int gt = blockIdx.x * 256 + threadIdx.x;
    const int lane = gt & 31;
    const int wg = gt >> 5;                // global warp id = run id, 0..255
    if (gt == 0) out[0] = 0.0f;
    float4 e = e4[gt];
    float n2 = e.x*e.x + e.y*e.y + e.z*e.z + e.w*e.w;
    bool c = (n2 >= THETA);
    unsigned m = __ballot_sync(0xFFFFFFFFu, c);
    int p = __popc(m & ((1u << lane) - 1u));
    if (c && p < RCAP) { d_stage[wg * RCAP + p] = e; d_sid[wg * RCAP + p] = gt; }
    if (lane == 0) d_bcnt[wg] = __popc(m); // may exceed RCAP -> over in B
}

// ---- Kernel B: compact+sort in smem, padded pruned scan, atomic loss ----
__global__ __launch_bounds__(NTHR, 1)
void vq_main_kernel(const float4* __restrict__ x4,
                    const float4* __restrict__ e4,
                    float* __restrict__ out) {
    __shared__ float4 s_stage[CAP];       // compacted (unsorted)
    __shared__ int    s_sid[CAP];
    __shared__ float4 s_tbl[CAP];         // bin-sorted (desc norm) + sentinel pad
    __shared__ int    s_sidx[CAP];
    __shared__ int    s_bc[NRUN], s_bo[NRUN];
    __shared__ int    s_hist[NB2], s_soff[NB2], s_scur[NB2];
    __shared__ float  s_ubs[NUBS];
    __shared__ float  wred[NTHR / 32];
    __shared__ int    s_over, s_cntA;

    const int t    = threadIdx.x;
    const int lane = t & 31;
    const int wid  = t >> 5;
    const int sub  = lane & 3;
    const int tok  = ((int)blockIdx.x * 28 + wid) * 8 + (lane >> 2);
    const bool act = tok < NTOK;

    float4 xv = act ? x4[tok] : make_float4(0.f, 0.f, 0.f, 0.f);
    const float nx = sqrtf(xv.x*xv.x + xv.y*xv.y + xv.z*xv.z + xv.w*xv.w)
                     * 1.000002f;                     // fp-guarded |x|

    if (t < NB2) { s_hist[t] = 0; s_scur[t] = 0; }
    if (t < NRUN) s_bc[t] = d_bcnt[t];
    __syncthreads();

    // prefix over 256 run-counts: warp 0, 8 runs per lane + shfl scan
    if (wid == 0) {
        int ex[8]; int ov = 0; int sum = 0;
        #pragma unroll
        for (int j = 0; j < 8; j++) {
            int c = s_bc[lane * 8 + j];
            if (c > RCAP) { ov = 1; c = RCAP; }
            ex[j] = sum; sum += c;
        }
        int v = sum;
        #pragma unroll
        for (int o = 1; o < 32; o <<= 1) {
            int u = __shfl_up_sync(0xFFFFFFFFu, v, o);
            if (lane >= o) v += u;
        }
        int base = v - sum;
        #pragma unroll
        for (int j = 0; j < 8; j++) s_bo[lane * 8 + j] = base + ex[j];
        ov = __any_sync(0xFFFFFFFFu, ov) ? 1 : 0;
        if (lane == 31) { s_cntA = v; s_over = ov; }
    }
    __syncthreads();

    const int  cnt_all = s_cntA;
    const bool over    = s_over || (cnt_all > CAP);   // ~never
    const int  cnt     = cnt_all < CAP ? cnt_all : CAP;
    const int  nsl     = (cnt + 31) & ~31;

    // copy ragged runs -> compact smem staging (thread r owns run r)
    if (t < NRUN) {
        int n = s_bc[t] < RCAP ? s_bc[t] : RCAP;
        int off = s_bo[t];
        for (int j = 0; j < n; j++) {
            int dst = off + j;
            if (dst < CAP) {
                s_stage[dst] = d_stage[t * RCAP + j];
                s_sid[dst]   = d_sid[t * RCAP + j];
            }
        }
    }
    __syncthreads();

    // histogram (validated path)
    #pragma unroll
    for (int r = 0; r < 2; r++) {
        int i = t + r * NTHR;
        if (i < cnt) {
            float4 e = s_stage[i];
            float n2 = e.x*e.x + e.y*e.y + e.z*e.z + e.w*e.w;
            int raw = (int)((n2 - THETA) * IW2);
            raw = raw < 0 ? 0 : (raw > NB2 - 1 ? NB2 - 1 : raw);
            atomicAdd(&s_hist[(NB2 - 1) - raw], 1);
        }
    }
    __syncthreads();

    // exclusive prefix over 64 bins (warp 0)
    if (wid == 0) {
        int a = s_hist[lane], b = s_hist[lane + 32];
        int va = a, vb = b;
        #pragma unroll
        for (int o = 1; o < 32; o <<= 1) {
            int u = __shfl_up_sync(0xFFFFFFFFu, va, o); if (lane >= o) va += u;
            int w = __shfl_up_sync(0xFFFFFFFFu, vb, o); if (lane >= o) vb += w;
        }
        int tot = __shfl_sync(0xFFFFFFFFu, va, 31);
        s_soff[lane]      = va - a;
        s_soff[lane + 32] = tot + vb - b;
    }
    __syncthreads();

    // scatter into bin-sorted order + superstep ub
    #pragma unroll
    for (int r = 0; r < 2; r++) {
        int i = t + r * NTHR;
        if (i < cnt) {
            float4 e = s_stage[i];
            float n2 = e.x*e.x + e.y*e.y + e.z*e.z + e.w*e.w;
            int raw = (int)((n2 - THETA) * IW2);
            raw = raw < 0 ? 0 : (raw > NB2 - 1 ? NB2 - 1 : raw);
            int b = (NB2 - 1) - raw;
            int pos = s_soff[b] + atomicAdd(&s_scur[b], 1);
            if (pos < CAP) {
                s_tbl[pos]  = e;
                s_sidx[pos] = s_sid[i];
                if ((pos & 31) == 0)    // ub for all slots >= pos
                    s_ubs[pos >> 5] = (b == 0) ? CUDART_INF_F
                        : sqrtf(THETA + (float)(NB2 - b) * WID2) * 1.000002f;
            }
        }
    }
    __syncthreads();

    // sentinel padding: dup slot 0 with id=NEMB. A pad can never change the
    // final (max value, min id): its value equals slot0's dot, and slot0's
    // lower id dominates every tie merge.
    if (t < 32) {
        int i = cnt + t;
        if (i < nsl) { s_tbl[i] = s_tbl[0]; s_sidx[i] = NEMB; }
    }
    __syncthreads();

    // ---- pruned scan: predicate-free body; tests hoisted past 128 slots ----
    float best = act ? -CUDART_INF_F : CUDART_INF_F;
    int bidx = NEMB;

    for (int p = 0; p < nsl; p += 32) {
        float d[8];
        #pragma unroll
        for (int i = 0; i < 8; i++) {
            float4 e = s_tbl[p + sub + 4 * i];        // 4 words/warp: broadcast
            d[i] = fmaf(xv.x, e.x, fmaf(xv.y, e.y, fmaf(xv.z, e.z, xv.w * e.w)));
        }
        float om = fmaxf(fmaxf(fmaxf(d[0], d[1]), fmaxf(d[2], d[3])),
                         fmaxf(fmaxf(d[4], d[5]), fmaxf(d[6], d[7])));
        if (om >= best) {
            // rare slow path: exact first-max update, original-id tie-break
            #pragma unroll
            for (int i = 0; i < 8; i++) {
                int id = s_sidx[p + sub + 4 * i];
                if (d[i] > best || (d[i] == best && id < bidx)) {
                    best = d[i]; bidx = id;
                }
            }
        }
        if (p >= 96) {                    // certificate ~never passes earlier
            float ubn = (p + 32 >= cnt) ? SQ8G : s_ubs[(p >> 5) + 1];
            float cb = best;              // quad-combined best value
            cb = fmaxf(cb, __shfl_xor_sync(0xFFFFFFFFu, cb, 1));
            cb = fmaxf(cb, __shfl_xor_sync(0xFFFFFFFFu, cb, 2));
            // remaining slots <= ubn; sub-theta mass <= SQ8G <= ubn
            if (!over && __all_sync(0xFFFFFFFFu, ubn * nx < cb)) break;
        }
    }

    // final certificate; ~never false for real data
    float cbf = best;
    cbf = fmaxf(cbf, __shfl_xor_sync(0xFFFFFFFFu, cbf, 1));
    cbf = fmaxf(cbf, __shfl_xor_sync(0xFFFFFFFFu, cbf, 2));
    bool needFB = over ? act : !(SQ8G * nx < cbf);

    // exact warp-cooperative full-table fallback (correctness backstop)
    unsigned m = __ballot_sync(0xFFFFFFFFu, needFB);
    while (m) {
        int l = __ffs(m) - 1; int q = l >> 2;
        m &= ~(0xFu << (q << 2));
        int ol = q << 2;
        float tx = __shfl_sync(0xFFFFFFFFu, xv.x, ol);
        float ty = __shfl_sync(0xFFFFFFFFu, xv.y, ol);
        float tz = __shfl_sync(0xFFFFFFFFu, xv.z, ol);
        float tw = __shfl_sync(0xFFFFFFFFu, xv.w, ol);
        float lb = -CUDART_INF_F;
        int lid = NEMB;
        for (int pp = 0; pp < NEMB; pp += 256) {
            #pragma unroll
            for (int i = 0; i < 8; i++) {
                int slot = pp + lane + (i << 5);
                float4 e = e4[slot];
                float dd = fmaf(tx, e.x, fmaf(ty, e.y, fmaf(tz, e.z, tw * e.w)));
                if (dd > lb || (dd == lb && slot < lid)) { lb = dd; lid = slot; }
            }
        }
        #pragma unroll
        for (int o = 16; o; o >>= 1) {
            float vo = __shfl_xor_sync(0xFFFFFFFFu, lb, o);
            int   io = __shfl_xor_sync(0xFFFFFFFFu, lid, o);
            if (vo > lb || (vo == lb && io < lid)) { lb = vo; lid = io; }
        }
        if ((lane >> 2) == q) {
            if (lb > best || (lb == best && lid < bidx)) { best = lb; bidx = lid; }
        }
    }

    // merge quad lanes: max value, ties -> lowest original index
    #pragma unroll
    for (int o = 1; o <= 2; o <<= 1) {
        float vo = __shfl_xor_sync(0xFFFFFFFFu, best, o);
        int   io = __shfl_xor_sync(0xFFFFFFFFu, bidx, o);
        if (vo > best || (vo == best && io < bidx)) { best = vo; bidx = io; }
    }

    float lsum = 0.0f;
    if (act && sub == 0) {
        float4 e = e4[bidx];
        lsum = fabsf(xv.x - e.x) + fabsf(xv.y - e.y)
             + fabsf(xv.z - e.z) + fabsf(xv.w - e.w);
    }

    // reduce: warp -> block -> ONE direct global atomic (out zeroed by A)
    #pragma unroll
    for (int o = 16; o; o >>= 1)
        lsum += __shfl_down_sync(0xFFFFFFFFu, lsum, o);
    if (lane == 0) wred[wid] = lsum;
    __syncthreads();
    if (t == 0) {
        float s = 0.0f;
        #pragma unroll
        for (int i = 0; i < NTHR / 32; i++) s += wred[i];
        atomicAdd(out, s * (2.0f / (float)(NTOK * 4)));  // both L1 terms equal
    }
}

extern "C" void kernel_launch(void* const* d_in, const int* in_sizes, int n_in,
                              void* d_out, int out_size) {
    const float4* x   = (const float4*)d_in[0];   // [8,4096,4] f32
    const float4* emb = (const float4*)d_in[1];   // [8192,4] f32
    float* out = (float*)d_out;

    vq_stage<<<NEMB / 256, 256>>>(emb, out);
    vq_main_kernel<<<NBLK, NTHR>>>(x, emb, out);
}